// round 14
// baseline (speedup 1.0000x reference)
#include <cuda_runtime.h>
#include <cuda_fp16.h>
#include <cstdint>
#include <math.h>

#define NPTS   65536
#define BATCH  4
#define DM     128
#define MLPW   256
#define NFREQ  10
#define IN0    170
#define MT     128
#define PI_F   3.14159265358979323846f

// A smem: 128 rows x 264 fp16 (stride 528B), hi plane only
#define ASTR   528
#define A_HI   0
// W buffers: 3 x (256 rows x 144B)  (K=64 fp16 = 128B data + 16B pad)
#define WB0    67584
#define WBUF   36864
// params
#define SM_G    178176
#define SM_BETA 179200
#define SM_BIAS 180224
#define SM_WO   184320      // w_out fp16, 8 n-rows x 256 k, stride 528B
#define SMEM_BYTES 188544

#define NTHR   512

__device__ __align__(128) __half g_wh[4*256*256];
__device__ float g_gamma1[BATCH*MLPW];
__device__ float g_beta[BATCH*MLPW];

__device__ __forceinline__ uint32_t smem_u32(const void* p) {
    uint32_t a;
    asm("{ .reg .u64 t; cvta.to.shared.u64 t, %1; cvt.u32.u64 %0, t; }" : "=r"(a) : "l"(p));
    return a;
}
__device__ __forceinline__ void cp16(uint32_t dst, const void* src) {
    asm volatile("cp.async.cg.shared.global [%0], [%1], 16;" :: "r"(dst), "l"(src));
}
#define CP_COMMIT() asm volatile("cp.async.commit_group;" ::: "memory")
template <int N> __device__ __forceinline__ void cp_wait() {
    asm volatile("cp.async.wait_group %0;" :: "n"(N) : "memory");
}
__device__ __forceinline__ void ldsm4(uint32_t* r, uint32_t addr) {
    asm volatile("ldmatrix.sync.aligned.m8n8.x4.shared.b16 {%0,%1,%2,%3}, [%4];"
                 : "=r"(r[0]), "=r"(r[1]), "=r"(r[2]), "=r"(r[3]) : "r"(addr));
}
__device__ __forceinline__ void ldsm2(uint32_t* r, uint32_t addr) {
    asm volatile("ldmatrix.sync.aligned.m8n8.x2.shared.b16 {%0,%1}, [%2];"
                 : "=r"(r[0]), "=r"(r[1]) : "r"(addr));
}
__device__ __forceinline__ void mma16816(float* c, const uint32_t* a, const uint32_t* b) {
    asm volatile("mma.sync.aligned.m16n8k16.row.col.f32.f16.f16.f32 "
                 "{%0,%1,%2,%3}, {%4,%5,%6,%7}, {%8,%9}, {%0,%1,%2,%3};"
                 : "+f"(c[0]), "+f"(c[1]), "+f"(c[2]), "+f"(c[3])
                 : "r"(a[0]), "r"(a[1]), "r"(a[2]), "r"(a[3]), "r"(b[0]), "r"(b[1]));
}
__device__ __forceinline__ float gelu_fast(float x) {
    float u = 0.7978845608028654f * fmaf(0.044715f * x, x * x, x);
    float e, rc;
    asm("ex2.approx.f32 %0, %1;" : "=f"(e) : "f"(u * 2.8853900817779268f));
    asm("rcp.approx.f32 %0, %1;" : "=f"(rc) : "f"(e + 1.0f));
    return x * (1.0f - rc);
}

// sample q-range [q0, q1): thread sub handles float4 index q*4+sub
template <int Q0, int Q1>
__device__ __forceinline__ void sample_q(const float* gb, char* hb, int sub,
                                         float w00, float w01, float w10, float w11) {
    const float4* q00 = (const float4*)gb;
    const float4* q01 = (const float4*)(gb + DM);
    const float4* q10 = (const float4*)(gb + 8192);
    const float4* q11 = (const float4*)(gb + 8192 + DM);
#pragma unroll
    for (int q = Q0; q < Q1; q++) {
        int f = q * 4 + sub;
        float4 A = __ldg(q00 + f), B = __ldg(q01 + f);
        float4 C = __ldg(q10 + f), D = __ldg(q11 + f);
        float v0 = w00*A.x + w01*B.x + w10*C.x + w11*D.x;
        float v1 = w00*A.y + w01*B.y + w10*C.y + w11*D.y;
        float v2 = w00*A.z + w01*B.z + w10*C.z + w11*D.z;
        float v3 = w00*A.w + w01*B.w + w10*C.w + w11*D.w;
        __half2 p0 = __floats2half2_rn(v0, v1);
        __half2 p1 = __floats2half2_rn(v2, v3);
        *(uint32_t*)(hb + 84 + 8 * f)     = *(uint32_t*)&p0;
        *(uint32_t*)(hb + 84 + 8 * f + 4) = *(uint32_t*)&p1;
    }
}

// ---------- prep: transpose W, round to fp16 ----------
__global__ void prep_w_kernel(const float* __restrict__ w0, const float* __restrict__ w1,
                              const float* __restrict__ w2, const float* __restrict__ w3) {
    int l = blockIdx.y, k = blockIdx.x, n = threadIdx.x;
    const float* w = (l == 0) ? w0 : (l == 1) ? w1 : (l == 2) ? w2 : w3;
    int kd = (l == 0) ? IN0 : MLPW;
    float v = (k < kd) ? w[k * MLPW + n] : 0.0f;
    g_wh[((size_t)l * 256 + n) * 256 + k] = __float2half_rn(v);
}

__global__ void film_kernel(const float* __restrict__ ctx,
                            const float* __restrict__ wf,
                            const float* __restrict__ bf) {
    int b = blockIdx.x, j = threadIdx.x;
    float acc = bf[j];
    const float* c = ctx + b * DM;
#pragma unroll 4
    for (int k = 0; k < DM; k++)
        acc = fmaf(__ldg(&c[k]), __ldg(&wf[k * 2 * MLPW + j]), acc);
    if (j < MLPW) g_gamma1[b * MLPW + j] = acc + 1.0f;
    else          g_beta[b * MLPW + (j - MLPW)] = acc;
}

// load W chunk (K=64 slice) for (layer l, local chunk c) into buffer buf (512 thr)
__device__ __forceinline__ void load_chunk(uint32_t base, int buf, int l, int c, int tid) {
    int row  = tid >> 1;
    int part = tid & 1;          // 64B half of the 128B row
    uint32_t d = base + WB0 + buf * WBUF + row * 144 + part * 64;
    const __half* s = g_wh + ((size_t)l * 256 + row) * 256 + c * 64 + part * 32;
    cp16(d, s);
    cp16(d + 16, s + 8);
    cp16(d + 32, s + 16);
    cp16(d + 48, s + 24);
}

// ---------- main kernel ----------
__global__ void __launch_bounds__(NTHR, 1)
decoder_kernel(const float* __restrict__ fgrid, const float* __restrict__ coords,
               const float* __restrict__ b0p, const float* __restrict__ b1p,
               const float* __restrict__ b2p, const float* __restrict__ b3p,
               const float* __restrict__ wo, const float* __restrict__ bo,
               float* __restrict__ out) {
    extern __shared__ char smc[];
    const uint32_t base = smem_u32(smc);
    const int tid  = threadIdx.x;
    const int w    = tid >> 5, lane = tid & 31;
    const int b    = blockIdx.y;
    const int n0g  = blockIdx.x * MT;
    const int m0   = (w & 1) * 64;           // warp M offset
    const int nw0  = (w >> 1) * 32;          // warp N offset (16 warps: 2x8)

    // lane-fixed ldmatrix offsets
    const int lg   = lane >> 3, lr = lane & 7;
    const int aRow = lr + ((lg & 1) << 3);
    const int aKh  = (lg >> 1) << 3;
    const int bN   = lr + ((lg >> 1) << 3);
    const int bKh  = (lg & 1) << 3;
    const uint32_t aOffH = base + A_HI + (uint32_t)(m0 + aRow) * ASTR + aKh * 2;
    const uint32_t bOff  = (uint32_t)(nw0 + bN) * 144 + bKh * 2;

    // prefetch first two W chunks of layer 0
    load_chunk(base, 0, 0, 0, tid); CP_COMMIT();
    load_chunk(base, 1, 0, 1, tid); CP_COMMIT();

    // stage params
    float* shg   = (float*)(smc + SM_G);
    float* shb   = (float*)(smc + SM_BETA);
    float* sbias = (float*)(smc + SM_BIAS);
    if (tid < 256) {
        shg[tid] = g_gamma1[b * MLPW + tid];
        shb[tid] = g_beta[b * MLPW + tid];
        sbias[tid]       = __ldg(&b0p[tid]);
        sbias[256 + tid] = __ldg(&b1p[tid]);
        sbias[512 + tid] = __ldg(&b2p[tid]);
        sbias[768 + tid] = __ldg(&b3p[tid]);
    }
    // stage w_out as fp16, padded to 8 n-rows x 256 k (n>=3 rows zero)
    {
#pragma unroll
        for (int e = 0; e < 4; e++) {
            int u = tid * 4 + e;          // 0..2047
            int n = u >> 8, k = u & 255;
            float v = (n < 3) ? __ldg(&wo[k * 3 + n]) : 0.0f;
            *(__half*)(smc + SM_WO + n * 528 + k * 2) = __float2half_rn(v);
        }
    }

    // ---------- phase A setup + minimal pre-loop sampling ----------
    // Layer-0 chunk g consumes A cols [64g,64g+64). Pre-loop provides enc
    // (cols 0..41) + q0,q1 (ch 42..73). q2..q5 pipeline under chunk 0,
    // q6,q7+pad under chunk 1.
    const int subA = tid & 3;
    float w00, w01, w10, w11;
    const float* gb;
    char* hbp;
    {
        int p = tid >> 2;
        int n = n0g + p;
        float cy = __ldg(&coords[2 * n]), cx = __ldg(&coords[2 * n + 1]);
        float py = fminf(fmaxf((cy + 1.0f) * 31.5f, 0.0f), 63.0f);
        float px = fminf(fmaxf((cx + 1.0f) * 31.5f, 0.0f), 63.0f);
        int y0i = min((int)py, 62), x0i = min((int)px, 62);
        float fy = py - (float)y0i, fx = px - (float)x0i;
        w00 = (1.f - fy) * (1.f - fx); w01 = (1.f - fy) * fx;
        w10 = fy * (1.f - fx);         w11 = fy * fx;
        gb  = fgrid + (((size_t)b * 64 + y0i) * 64 + x0i) * DM;
        hbp = smc + A_HI + p * ASTR;
#define PUT(j, v) do { *(__half*)(hbp + 2*(j)) = __float2half_rn(v); } while(0)
        if (subA == 0) {
            PUT(0, cy); PUT(1, cx);
            float sy, cyv, sx, cxv;
            sincosf(PI_F * cy, &sy, &cyv);
            sincosf(PI_F * cx, &sx, &cxv);
#pragma unroll
            for (int i = 0; i < NFREQ; i++) {
                PUT(2 + 4*i + 0, sy);  PUT(2 + 4*i + 1, sx);
                PUT(2 + 4*i + 2, cyv); PUT(2 + 4*i + 3, cxv);
                float ns = 2.f * sy * cyv, nc = 1.f - 2.f * sy * sy;
                sy = ns; cyv = nc;
                ns = 2.f * sx * cxv; nc = 1.f - 2.f * sx * sx;
                sx = ns; cxv = nc;
            }
        }
#undef PUT
        sample_q<0, 2>(gb, hbp, subA, w00, w01, w10, w11);
    }
    __syncthreads();

    // ---------- mainloop: 15 K=64 chunks over 4 layers, single pass ----------
    float acc[4][4][4];
#pragma unroll
    for (int i = 0; i < 4; i++)
#pragma unroll
        for (int j = 0; j < 4; j++)
#pragma unroll
            for (int r = 0; r < 4; r++) acc[i][j][r] = 0.0f;

    int layer = 0, cloc = 0, nch = 3;
#pragma unroll 1
    for (int g = 0; g < 15; g++) {
        cp_wait<1>();
        __syncthreads();
        // prefetch chunk g+2
        {
            int j = g + 2;
            if (j < 15) {
                int ln = (j < 3) ? 0 : (j - 3) / 4 + 1;
                int cn = (ln == 0) ? j : (j - 3) & 3;
                load_chunk(base, j % 3, ln, cn, tid);
            }
            CP_COMMIT();
        }
        // MMAs for chunk g (K=64: four k-subtiles of 16)
        {
            const uint32_t wb = base + WB0 + (uint32_t)(g % 3) * WBUF;
            const uint32_t k2 = (uint32_t)cloc * 128;
            uint32_t af[4][4], bfr[2][4];
#pragma unroll
            for (int ks = 0; ks < 4; ks++) {
                const uint32_t kb = k2 + (uint32_t)ks * 32;
#pragma unroll
                for (int j2 = 0; j2 < 2; j2++)
                    ldsm4(bfr[j2], wb + bOff + (uint32_t)ks * 32 + j2 * 2304);
#pragma unroll
                for (int i = 0; i < 4; i++) ldsm4(af[i], aOffH + i * (16 * ASTR) + kb);
#pragma unroll
                for (int i = 0; i < 4; i++)
#pragma unroll
                    for (int j = 0; j < 4; j++)
                        mma16816(acc[i][j], af[i], &bfr[j >> 1][(j & 1) * 2]);
            }
        }
        // pipelined remainder of phase A (hidden under layer-0 tensor work;
        // next iteration's __syncthreads orders these STS before their ldsm)
        if (g == 0) {
            sample_q<2, 6>(gb, hbp, subA, w00, w01, w10, w11);
        } else if (g == 1) {
            sample_q<6, 8>(gb, hbp, subA, w00, w01, w10, w11);
            if (subA == 3) {
#pragma unroll
                for (int q2 = 0; q2 < 11; q2++)
                    *(uint32_t*)(hbp + 340 + 4*q2) = 0u;
            }
        }
        cloc++;
        if (cloc == nch) {
            // ---------- layer epilogue ----------
            const float* bl = sbias + layer * 256;
            const int cb = nw0 + 2 * (lane & 3);
            const int rb = m0 + (lane >> 2);
            // 1) gelu in place (before barrier: overlaps warp arrival skew)
#pragma unroll
            for (int j = 0; j < 4; j++) {
                int col = cb + 8 * j;
                float bi0 = bl[col], bi1 = bl[col + 1];
                float gg0 = shg[col], gg1 = shg[col + 1];
                float be0 = shb[col], be1 = shb[col + 1];
#pragma unroll
                for (int i = 0; i < 4; i++) {
                    acc[i][j][0] = gelu_fast(fmaf(acc[i][j][0] + bi0, gg0, be0));
                    acc[i][j][1] = gelu_fast(fmaf(acc[i][j][1] + bi1, gg1, be1));
                    acc[i][j][2] = gelu_fast(fmaf(acc[i][j][2] + bi0, gg0, be0));
                    acc[i][j][3] = gelu_fast(fmaf(acc[i][j][3] + bi1, gg1, be1));
                }
            }
            // 2) barrier: all warps done reading A for this layer
            __syncthreads();
            // 3) store to A hi plane, reset acc
#pragma unroll
            for (int j = 0; j < 4; j++) {
                int col = cb + 8 * j;
#pragma unroll
                for (int i = 0; i < 4; i++) {
                    int row = rb + 16 * i;
                    __half2 h0 = __floats2half2_rn(acc[i][j][0], acc[i][j][1]);
                    __half2 h1 = __floats2half2_rn(acc[i][j][2], acc[i][j][3]);
                    acc[i][j][0] = 0.0f; acc[i][j][1] = 0.0f;
                    acc[i][j][2] = 0.0f; acc[i][j][3] = 0.0f;
                    uint32_t o0 = (uint32_t)row * ASTR + (uint32_t)col * 2;
                    *(uint32_t*)(smc + A_HI + o0) = *(uint32_t*)&h0;
                    *(uint32_t*)(smc + A_HI + o0 + 8 * ASTR) = *(uint32_t*)&h1;
                }
            }
            layer++; cloc = 0; nch = 4;
        }
    }
    __syncthreads();

    // ---------- head: 128x8x256 fp16 MMA (warps 0-7, 16 rows each) ----------
    if (w < 8) {
        float hc[4] = {0.0f, 0.0f, 0.0f, 0.0f};
        const uint32_t aaddr = base + A_HI + (uint32_t)(w * 16 + aRow) * ASTR + aKh * 2;
        const uint32_t baddr = base + SM_WO + (uint32_t)(lane & 7) * 528
                               + ((uint32_t)((lane >> 3) & 1)) * 16;
#pragma unroll
        for (int ks = 0; ks < 16; ks++) {
            uint32_t af[4], bf2[2];
            ldsm4(af, aaddr + ks * 32);
            ldsm2(bf2, baddr + ks * 32);
            mma16816(hc, af, bf2);
        }
        int row = w * 16 + (lane >> 2);
        int col = (lane & 3) * 2;
        if (col < 3) {
            size_t ob = (size_t)b * NPTS + n0g;
            float bc0 = __ldg(&bo[col]);
            out[(ob + row) * 3 + col]     = tanhf(hc[0] + bc0);
            out[(ob + row + 8) * 3 + col] = tanhf(hc[2] + bc0);
            if (col + 1 < 3) {
                float bc1 = __ldg(&bo[col + 1]);
                out[(ob + row) * 3 + col + 1]     = tanhf(hc[1] + bc1);
                out[(ob + row + 8) * 3 + col + 1] = tanhf(hc[3] + bc1);
            }
        }
    }
}

extern "C" void kernel_launch(void* const* d_in, const int* in_sizes, int n_in,
                              void* d_out, int out_size) {
    const float* fgrid  = (const float*)d_in[0];
    const float* ctx    = (const float*)d_in[1];
    const float* coords = (const float*)d_in[2];
    const float* w0 = (const float*)d_in[3];
    const float* b0 = (const float*)d_in[4];
    const float* w1 = (const float*)d_in[5];
    const float* b1 = (const float*)d_in[6];
    const float* w2 = (const float*)d_in[7];
    const float* b2 = (const float*)d_in[8];
    const float* w3 = (const float*)d_in[9];
    const float* b3 = (const float*)d_in[10];
    const float* wf = (const float*)d_in[11];
    const float* bf = (const float*)d_in[12];
    const float* wo = (const float*)d_in[13];
    const float* bo = (const float*)d_in[14];
    float* out = (float*)d_out;

    cudaFuncSetAttribute(decoder_kernel,
                         cudaFuncAttributeMaxDynamicSharedMemorySize, SMEM_BYTES);

    dim3 pgrid(256, 4);
    prep_w_kernel<<<pgrid, 256>>>(w0, w1, w2, w3);
    film_kernel<<<BATCH, 2 * MLPW>>>(ctx, wf, bf);
    dim3 grid(NPTS / MT, BATCH);
    decoder_kernel<<<grid, NTHR, SMEM_BYTES>>>(fgrid, coords, b0, b1, b2, b3,
                                               wo, bo, out);
}

// round 15
// speedup vs baseline: 1.1072x; 1.1072x over previous
#include <cuda_runtime.h>
#include <cuda_fp16.h>
#include <cstdint>
#include <math.h>

#define NPTS   65536
#define BATCH  4
#define DM     128
#define MLPW   256
#define NFREQ  10
#define IN0    170
#define MT     128
#define PI_F   3.14159265358979323846f

// A smem: 128 rows x 264 fp16 (stride 528B), hi plane only
#define ASTR   528
#define A_HI   0
// W buffers: 3 x (256 rows x 144B)  (K=64 fp16 = 128B data + 16B pad)
#define WB0    67584
#define WBUF   36864
// params
#define SM_G    178176
#define SM_BETA 179200
#define SM_BIAS 180224
#define SM_WO   184320      // w_out fp16, 8 n-rows x 256 k, stride 528B
#define SMEM_BYTES 188544

#define NTHR   512

__device__ __align__(128) __half g_wh[4*256*256];
__device__ float g_gamma1[BATCH*MLPW];
__device__ float g_beta[BATCH*MLPW];

__device__ __forceinline__ uint32_t smem_u32(const void* p) {
    uint32_t a;
    asm("{ .reg .u64 t; cvta.to.shared.u64 t, %1; cvt.u32.u64 %0, t; }" : "=r"(a) : "l"(p));
    return a;
}
__device__ __forceinline__ void cp16(uint32_t dst, const void* src) {
    asm volatile("cp.async.cg.shared.global [%0], [%1], 16;" :: "r"(dst), "l"(src));
}
#define CP_COMMIT() asm volatile("cp.async.commit_group;" ::: "memory")
template <int N> __device__ __forceinline__ void cp_wait() {
    asm volatile("cp.async.wait_group %0;" :: "n"(N) : "memory");
}
__device__ __forceinline__ void ldsm4(uint32_t* r, uint32_t addr) {
    asm volatile("ldmatrix.sync.aligned.m8n8.x4.shared.b16 {%0,%1,%2,%3}, [%4];"
                 : "=r"(r[0]), "=r"(r[1]), "=r"(r[2]), "=r"(r[3]) : "r"(addr));
}
__device__ __forceinline__ void ldsm2(uint32_t* r, uint32_t addr) {
    asm volatile("ldmatrix.sync.aligned.m8n8.x2.shared.b16 {%0,%1}, [%2];"
                 : "=r"(r[0]), "=r"(r[1]) : "r"(addr));
}
__device__ __forceinline__ void mma16816(float* c, const uint32_t* a, const uint32_t* b) {
    asm volatile("mma.sync.aligned.m16n8k16.row.col.f32.f16.f16.f32 "
                 "{%0,%1,%2,%3}, {%4,%5,%6,%7}, {%8,%9}, {%0,%1,%2,%3};"
                 : "+f"(c[0]), "+f"(c[1]), "+f"(c[2]), "+f"(c[3])
                 : "r"(a[0]), "r"(a[1]), "r"(a[2]), "r"(a[3]), "r"(b[0]), "r"(b[1]));
}
// gelu with single-MUFU tanh.approx (max abs err ~2^-10.7 on tanh)
__device__ __forceinline__ float gelu_fast(float x) {
    float u = 0.7978845608028654f * fmaf(0.044715f * x, x * x, x);
    float t;
    asm("tanh.approx.f32 %0, %1;" : "=f"(t) : "f"(u));
    return 0.5f * x * (1.0f + t);
}

// ---------- prep: transpose W, round to fp16 ----------
__global__ void prep_w_kernel(const float* __restrict__ w0, const float* __restrict__ w1,
                              const float* __restrict__ w2, const float* __restrict__ w3) {
    int l = blockIdx.y, k = blockIdx.x, n = threadIdx.x;
    const float* w = (l == 0) ? w0 : (l == 1) ? w1 : (l == 2) ? w2 : w3;
    int kd = (l == 0) ? IN0 : MLPW;
    float v = (k < kd) ? w[k * MLPW + n] : 0.0f;
    g_wh[((size_t)l * 256 + n) * 256 + k] = __float2half_rn(v);
}

__global__ void film_kernel(const float* __restrict__ ctx,
                            const float* __restrict__ wf,
                            const float* __restrict__ bf) {
    int b = blockIdx.x, j = threadIdx.x;
    float acc = bf[j];
    const float* c = ctx + b * DM;
#pragma unroll 4
    for (int k = 0; k < DM; k++)
        acc = fmaf(__ldg(&c[k]), __ldg(&wf[k * 2 * MLPW + j]), acc);
    if (j < MLPW) g_gamma1[b * MLPW + j] = acc + 1.0f;
    else          g_beta[b * MLPW + (j - MLPW)] = acc;
}

// load W chunk (K=64 slice) for (layer l, local chunk c) into buffer buf (512 thr)
__device__ __forceinline__ void load_chunk(uint32_t base, int buf, int l, int c, int tid) {
    int row  = tid >> 1;
    int part = tid & 1;          // 64B half of the 128B row
    uint32_t d = base + WB0 + buf * WBUF + row * 144 + part * 64;
    const __half* s = g_wh + ((size_t)l * 256 + row) * 256 + c * 64 + part * 32;
    cp16(d, s);
    cp16(d + 16, s + 8);
    cp16(d + 32, s + 16);
    cp16(d + 48, s + 24);
}

// ---------- main kernel ----------
__global__ void __launch_bounds__(NTHR, 1)
decoder_kernel(const float* __restrict__ fgrid, const float* __restrict__ coords,
               const float* __restrict__ b0p, const float* __restrict__ b1p,
               const float* __restrict__ b2p, const float* __restrict__ b3p,
               const float* __restrict__ wo, const float* __restrict__ bo,
               float* __restrict__ out) {
    extern __shared__ char smc[];
    const uint32_t base = smem_u32(smc);
    const int tid  = threadIdx.x;
    const int w    = tid >> 5, lane = tid & 31;
    const int b    = blockIdx.y;
    const int n0g  = blockIdx.x * MT;
    const int m0   = (w & 1) * 64;           // warp M offset
    const int nw0  = (w >> 1) * 32;          // warp N offset (16 warps: 2x8)

    // lane-fixed ldmatrix offsets
    const int lg   = lane >> 3, lr = lane & 7;
    const int aRow = lr + ((lg & 1) << 3);
    const int aKh  = (lg >> 1) << 3;
    const int bN   = lr + ((lg >> 1) << 3);
    const int bKh  = (lg & 1) << 3;
    const uint32_t aOffH = base + A_HI + (uint32_t)(m0 + aRow) * ASTR + aKh * 2;
    const uint32_t bOff  = (uint32_t)(nw0 + bN) * 144 + bKh * 2;

    // prefetch first two W chunks of layer 0
    load_chunk(base, 0, 0, 0, tid); CP_COMMIT();
    load_chunk(base, 1, 0, 1, tid); CP_COMMIT();

    // stage params
    float* shg   = (float*)(smc + SM_G);
    float* shb   = (float*)(smc + SM_BETA);
    float* sbias = (float*)(smc + SM_BIAS);
    if (tid < 256) {
        shg[tid] = g_gamma1[b * MLPW + tid];
        shb[tid] = g_beta[b * MLPW + tid];
        sbias[tid]       = __ldg(&b0p[tid]);
        sbias[256 + tid] = __ldg(&b1p[tid]);
        sbias[512 + tid] = __ldg(&b2p[tid]);
        sbias[768 + tid] = __ldg(&b3p[tid]);
    }
    // stage w_out as fp16, padded to 8 n-rows x 256 k (n>=3 rows zero)
    {
#pragma unroll
        for (int e = 0; e < 4; e++) {
            int u = tid * 4 + e;          // 0..2047
            int n = u >> 8, k = u & 255;
            float v = (n < 3) ? __ldg(&wo[k * 3 + n]) : 0.0f;
            *(__half*)(smc + SM_WO + n * 528 + k * 2) = __float2half_rn(v);
        }
    }

    // ---------- phase A: enc + bilinear sample (4 thr/point, interleaved f4) ----------
    {
        int p = tid >> 2, sub = tid & 3;
        int n = n0g + p;
        float cy = __ldg(&coords[2 * n]), cx = __ldg(&coords[2 * n + 1]);
        float py = fminf(fmaxf((cy + 1.0f) * 31.5f, 0.0f), 63.0f);
        float px = fminf(fmaxf((cx + 1.0f) * 31.5f, 0.0f), 63.0f);
        int y0i = min((int)py, 62), x0i = min((int)px, 62);
        float fy = py - (float)y0i, fx = px - (float)x0i;
        float w00 = (1.f - fy) * (1.f - fx), w01 = (1.f - fy) * fx;
        float w10 = fy * (1.f - fx), w11 = fy * fx;
        const float* gb = fgrid + (((size_t)b * 64 + y0i) * 64 + x0i) * DM;
        char* hb = smc + A_HI + p * ASTR;
        const float4* q00 = (const float4*)gb;
        const float4* q01 = (const float4*)(gb + DM);
        const float4* q10 = (const float4*)(gb + 8192);
        const float4* q11 = (const float4*)(gb + 8192 + DM);
        // interleaved: thread sub handles float4 indices q*4+sub
#pragma unroll
        for (int q = 0; q < 8; q++) {
            int f = q * 4 + sub;
            float4 A = __ldg(q00 + f), B = __ldg(q01 + f);
            float4 C = __ldg(q10 + f), D = __ldg(q11 + f);
            float v0 = w00*A.x + w01*B.x + w10*C.x + w11*D.x;
            float v1 = w00*A.y + w01*B.y + w10*C.y + w11*D.y;
            float v2 = w00*A.z + w01*B.z + w10*C.z + w11*D.z;
            float v3 = w00*A.w + w01*B.w + w10*C.w + w11*D.w;
            __half2 p0 = __floats2half2_rn(v0, v1);
            __half2 p1 = __floats2half2_rn(v2, v3);
            *(uint32_t*)(hb + 84 + 8 * f)     = *(uint32_t*)&p0;
            *(uint32_t*)(hb + 84 + 8 * f + 4) = *(uint32_t*)&p1;
        }
#define PUT(j, v) do { *(__half*)(hb + 2*(j)) = __float2half_rn(v); } while(0)
        if (sub == 0) {
            PUT(0, cy); PUT(1, cx);
            float sy, cyv, sx, cxv;
            sincosf(PI_F * cy, &sy, &cyv);
            sincosf(PI_F * cx, &sx, &cxv);
#pragma unroll
            for (int i = 0; i < NFREQ; i++) {
                PUT(2 + 4*i + 0, sy);  PUT(2 + 4*i + 1, sx);
                PUT(2 + 4*i + 2, cyv); PUT(2 + 4*i + 3, cxv);
                float ns = 2.f * sy * cyv, nc = 1.f - 2.f * sy * sy;
                sy = ns; cyv = nc;
                ns = 2.f * sx * cxv; nc = 1.f - 2.f * sx * sx;
                sx = ns; cxv = nc;
            }
        } else if (sub == 3) {
            // zero pad cols 170..191 (bytes 340..384, 4B-aligned)
#pragma unroll
            for (int q2 = 0; q2 < 11; q2++)
                *(uint32_t*)(hb + 340 + 4*q2) = 0u;
        }
#undef PUT
    }
    __syncthreads();

    // ---------- mainloop: 15 K=64 chunks over 4 layers, single pass ----------
    float acc[4][4][4];
#pragma unroll
    for (int i = 0; i < 4; i++)
#pragma unroll
        for (int j = 0; j < 4; j++)
#pragma unroll
            for (int r = 0; r < 4; r++) acc[i][j][r] = 0.0f;

    int layer = 0, cloc = 0, nch = 3;
#pragma unroll 1
    for (int g = 0; g < 15; g++) {
        cp_wait<1>();
        __syncthreads();
        // prefetch chunk g+2
        {
            int j = g + 2;
            if (j < 15) {
                int ln = (j < 3) ? 0 : (j - 3) / 4 + 1;
                int cn = (ln == 0) ? j : (j - 3) & 3;
                load_chunk(base, j % 3, ln, cn, tid);
            }
            CP_COMMIT();
        }
        // MMAs for chunk g (K=64: four k-subtiles of 16)
        {
            const uint32_t wb = base + WB0 + (uint32_t)(g % 3) * WBUF;
            const uint32_t k2 = (uint32_t)cloc * 128;
            uint32_t af[4][4], bfr[2][4];
#pragma unroll
            for (int ks = 0; ks < 4; ks++) {
                const uint32_t kb = k2 + (uint32_t)ks * 32;
#pragma unroll
                for (int j2 = 0; j2 < 2; j2++)
                    ldsm4(bfr[j2], wb + bOff + (uint32_t)ks * 32 + j2 * 2304);
#pragma unroll
                for (int i = 0; i < 4; i++) ldsm4(af[i], aOffH + i * (16 * ASTR) + kb);
#pragma unroll
                for (int i = 0; i < 4; i++)
#pragma unroll
                    for (int j = 0; j < 4; j++)
                        mma16816(acc[i][j], af[i], &bfr[j >> 1][(j & 1) * 2]);
            }
        }
        cloc++;
        if (cloc == nch) {
            // ---------- layer epilogue ----------
            const float* bl = sbias + layer * 256;
            const int cb = nw0 + 2 * (lane & 3);
            const int rb = m0 + (lane >> 2);
            // 1) gelu in place (before barrier: overlaps warp arrival skew)
#pragma unroll
            for (int j = 0; j < 4; j++) {
                int col = cb + 8 * j;
                float bi0 = bl[col], bi1 = bl[col + 1];
                float gg0 = shg[col], gg1 = shg[col + 1];
                float be0 = shb[col], be1 = shb[col + 1];
#pragma unroll
                for (int i = 0; i < 4; i++) {
                    acc[i][j][0] = gelu_fast(fmaf(acc[i][j][0] + bi0, gg0, be0));
                    acc[i][j][1] = gelu_fast(fmaf(acc[i][j][1] + bi1, gg1, be1));
                    acc[i][j][2] = gelu_fast(fmaf(acc[i][j][2] + bi0, gg0, be0));
                    acc[i][j][3] = gelu_fast(fmaf(acc[i][j][3] + bi1, gg1, be1));
                }
            }
            // 2) barrier: all warps done reading A for this layer
            __syncthreads();
            // 3) store to A hi plane, reset acc
#pragma unroll
            for (int j = 0; j < 4; j++) {
                int col = cb + 8 * j;
#pragma unroll
                for (int i = 0; i < 4; i++) {
                    int row = rb + 16 * i;
                    __half2 h0 = __floats2half2_rn(acc[i][j][0], acc[i][j][1]);
                    __half2 h1 = __floats2half2_rn(acc[i][j][2], acc[i][j][3]);
                    acc[i][j][0] = 0.0f; acc[i][j][1] = 0.0f;
                    acc[i][j][2] = 0.0f; acc[i][j][3] = 0.0f;
                    uint32_t o0 = (uint32_t)row * ASTR + (uint32_t)col * 2;
                    *(uint32_t*)(smc + A_HI + o0) = *(uint32_t*)&h0;
                    *(uint32_t*)(smc + A_HI + o0 + 8 * ASTR) = *(uint32_t*)&h1;
                }
            }
            layer++; cloc = 0; nch = 4;
        }
    }
    __syncthreads();

    // ---------- head: 128x8x256 fp16 MMA (warps 0-7, 16 rows each) ----------
    if (w < 8) {
        float hc[4] = {0.0f, 0.0f, 0.0f, 0.0f};
        const uint32_t aaddr = base + A_HI + (uint32_t)(w * 16 + aRow) * ASTR + aKh * 2;
        const uint32_t baddr = base + SM_WO + (uint32_t)(lane & 7) * 528
                               + ((uint32_t)((lane >> 3) & 1)) * 16;
#pragma unroll
        for (int ks = 0; ks < 16; ks++) {
            uint32_t af[4], bf2[2];
            ldsm4(af, aaddr + ks * 32);
            ldsm2(bf2, baddr + ks * 32);
            mma16816(hc, af, bf2);
        }
        int row = w * 16 + (lane >> 2);
        int col = (lane & 3) * 2;
        if (col < 3) {
            size_t ob = (size_t)b * NPTS + n0g;
            float bc0 = __ldg(&bo[col]);
            out[(ob + row) * 3 + col]     = tanhf(hc[0] + bc0);
            out[(ob + row + 8) * 3 + col] = tanhf(hc[2] + bc0);
            if (col + 1 < 3) {
                float bc1 = __ldg(&bo[col + 1]);
                out[(ob + row) * 3 + col + 1]     = tanhf(hc[1] + bc1);
                out[(ob + row + 8) * 3 + col + 1] = tanhf(hc[3] + bc1);
            }
        }
    }
}

extern "C" void kernel_launch(void* const* d_in, const int* in_sizes, int n_in,
                              void* d_out, int out_size) {
    const float* fgrid  = (const float*)d_in[0];
    const float* ctx    = (const float*)d_in[1];
    const float* coords = (const float*)d_in[2];
    const float* w0 = (const float*)d_in[3];
    const float* b0 = (const float*)d_in[4];
    const float* w1 = (const float*)d_in[5];
    const float* b1 = (const float*)d_in[6];
    const float* w2 = (const float*)d_in[7];
    const float* b2 = (const float*)d_in[8];
    const float* w3 = (const float*)d_in[9];
    const float* b3 = (const float*)d_in[10];
    const float* wf = (const float*)d_in[11];
    const float* bf = (const float*)d_in[12];
    const float* wo = (const float*)d_in[13];
    const float* bo = (const float*)d_in[14];
    float* out = (float*)d_out;

    cudaFuncSetAttribute(decoder_kernel,
                         cudaFuncAttributeMaxDynamicSharedMemorySize, SMEM_BYTES);

    dim3 pgrid(256, 4);
    prep_w_kernel<<<pgrid, 256>>>(w0, w1, w2, w3);
    film_kernel<<<BATCH, 2 * MLPW>>>(ctx, wf, bf);
    dim3 grid(NPTS / MT, BATCH);
    decoder_kernel<<<grid, NTHR, SMEM_BYTES>>>(fgrid, coords, b0, b1, b2, b3,
                                               wo, bo, out);
}